// round 1
// baseline (speedup 1.0000x reference)
#include <cuda_runtime.h>
#include <cstdint>

#define KTAGS 16
#define TLEN  512
#define BROWS 1024
#define START_ID 14
#define STOP_ID  15

__device__ float g_row_out[BROWS];
__device__ int   g_yshift;   // 1 if y is int64 (stride 2 in int32 words), 0 if int32

// ---------------------------------------------------------------------------
// Kernel 0: detect y dtype. If y is int64, every high 32-bit word is 0
// (values are 0..15). If y is int32, odd-index entries (tags 1..14) make the
// high half of the aliased u64 words nonzero almost surely.
// ---------------------------------------------------------------------------
__global__ void detect_y_kernel(const unsigned long long* __restrict__ y) {
    unsigned hi = 0;
    for (int k = threadIdx.x; k < 4096; k += 32)
        hi |= (unsigned)(y[k] >> 32);
    unsigned any = __ballot_sync(0xFFFFFFFFu, hi != 0);
    if (threadIdx.x == 0)
        g_yshift = (any != 0) ? 0 : 1;
}

// ---------------------------------------------------------------------------
// Kernel 1: per-row CRF forward score + gold score.
// One half-warp (16 lanes == 16 tags) per batch row. 64 threads/block ->
// 4 rows/block, 256 blocks.
// ---------------------------------------------------------------------------
__global__ void __launch_bounds__(64)
crf_main_kernel(const float* __restrict__ h,
                const int*   __restrict__ y32,       // raw y words (int32 view)
                const float* __restrict__ mask,
                const float* __restrict__ trans) {
    __shared__ float tr_s[256];
    __shared__ float pbuf[4][32];   // per group: double-buffered 16-float slot

    const int tid  = threadIdx.x;
    for (int i = tid; i < 256; i += 64) tr_s[i] = trans[i];
    __syncthreads();

    const int lane = tid & 15;
    const int gid  = tid >> 4;                 // 0..3 group in block
    const int row  = blockIdx.x * 4 + gid;
    const unsigned gmask = 0xFFFFu << (((tid >> 4) & 1) * 16);

    const float* hrow = h    + (size_t)row * TLEN * KTAGS;
    const float* mrow = mask + (size_t)row * TLEN;
    const int ysh = g_yshift;                              // 0 or 1
    const int* yrow = y32 + (((size_t)row * TLEN) << ysh); // index k -> yrow[k<<ysh]

    // Etr[j=lane][i] = exp(trans[j,i]) held in registers; exp(-1e4) flushes to 0.
    float Etr[16];
#pragma unroll
    for (int i = 0; i < 16; i++) Etr[i] = __expf(tr_s[lane * 16 + i]);
    const float EtrStop = __expf(tr_s[STOP_ID * 16 + lane]);

    // ---- length + gold score (lane-parallel over timesteps) ----
    float lsum = 0.f, gsum = 0.f;
    for (int k = lane; k < TLEN; k += 16) {
        float mk = mrow[k];
        lsum += mk;
        if (mk != 0.f) {
            int yt = yrow[k << ysh];
            int yp = (k == 0) ? START_ID : yrow[(k - 1) << ysh];
            gsum += hrow[k * 16 + yt] + tr_s[yt * 16 + yp];
        }
    }
#pragma unroll
    for (int s = 8; s; s >>= 1) {
        lsum += __shfl_xor_sync(gmask, lsum, s, 16);
        gsum += __shfl_xor_sync(gmask, gsum, s, 16);
    }
    const int len = (int)(lsum + 0.5f);
    const int lastTag = yrow[(len - 1) << ysh];
    const float gold = gsum + tr_s[STOP_ID * 16 + lastTag];

    // ---- forward recursion in linear domain ----
    // invariant: alpha_j = C + ln(p_j)
    float p = (lane == START_ID) ? 1.0f : 0.0f;
    float C = 0.0f;
    float emitE = __expf(hrow[lane]);   // exp(h[row, 0, lane])

    for (int t = 0; t < len; t++) {
        float* buf = pbuf[gid] + (t & 1) * 16;
        buf[lane] = p;

        // prefetch next emit early (off the dependency chain)
        const bool more = (t + 1 < len);
        float hn = 0.f;
        if (more) hn = hrow[(t + 1) * 16 + lane];

        __syncwarp(gmask);

        const float4 P0 = ((const float4*)buf)[0];
        const float4 P1 = ((const float4*)buf)[1];
        const float4 P2 = ((const float4*)buf)[2];
        const float4 P3 = ((const float4*)buf)[3];

        float s0 = P0.x * Etr[0];
        s0 = fmaf(P0.y, Etr[1],  s0);
        s0 = fmaf(P0.z, Etr[2],  s0);
        s0 = fmaf(P0.w, Etr[3],  s0);
        float s1 = P1.x * Etr[4];
        s1 = fmaf(P1.y, Etr[5],  s1);
        s1 = fmaf(P1.z, Etr[6],  s1);
        s1 = fmaf(P1.w, Etr[7],  s1);
        float s2 = P2.x * Etr[8];
        s2 = fmaf(P2.y, Etr[9],  s2);
        s2 = fmaf(P2.z, Etr[10], s2);
        s2 = fmaf(P2.w, Etr[11], s2);
        float s3 = P3.x * Etr[12];
        s3 = fmaf(P3.y, Etr[13], s3);
        s3 = fmaf(P3.z, Etr[14], s3);
        s3 = fmaf(P3.w, Etr[15], s3);
        const float S = (s0 + s1) + (s2 + s3);

        p = S * emitE;
        emitE = __expf(hn);    // harmless garbage compute when !more

        if ((t & 3) == 3) {    // amortized renormalization
            float r = p;
#pragma unroll
            for (int s = 8; s; s >>= 1)
                r = fmaxf(r, __shfl_xor_sync(gmask, r, s, 16));
            C += __logf(r);
            p = __fdividef(p, r);
        }
    }

    // fwd = C + ln( sum_j p_j * exp(trans[STOP, j]) )
    float v = p * EtrStop;
#pragma unroll
    for (int s = 8; s; s >>= 1)
        v += __shfl_xor_sync(gmask, v, s, 16);
    const float fwd = C + __logf(v);

    if (lane == 0) g_row_out[row] = fwd - gold;
}

// ---------------------------------------------------------------------------
// Kernel 2: mean over the 1024 per-row results.
// ---------------------------------------------------------------------------
__global__ void __launch_bounds__(256)
reduce_kernel(float* __restrict__ out) {
    __shared__ float sh[8];
    const int tid = threadIdx.x;
    float s = 0.f;
    for (int i = tid; i < BROWS; i += 256) s += g_row_out[i];
#pragma unroll
    for (int sft = 16; sft; sft >>= 1)
        s += __shfl_xor_sync(0xFFFFFFFFu, s, sft);
    if ((tid & 31) == 0) sh[tid >> 5] = s;
    __syncthreads();
    if (tid < 8) {
        float v = sh[tid];
#pragma unroll
        for (int sft = 4; sft; sft >>= 1)
            v += __shfl_xor_sync(0x000000FFu, v, sft, 8);
        if (tid == 0) out[0] = v * (1.0f / (float)BROWS);
    }
}

// ---------------------------------------------------------------------------
extern "C" void kernel_launch(void* const* d_in, const int* in_sizes, int n_in,
                              void* d_out, int out_size) {
    const float* h     = (const float*)d_in[0];
    const void*  y     = d_in[1];
    const float* mask  = (const float*)d_in[2];
    const float* trans = (const float*)d_in[3];
    float* out = (float*)d_out;

    detect_y_kernel<<<1, 32>>>((const unsigned long long*)y);
    crf_main_kernel<<<BROWS / 4, 64>>>(h, (const int*)y, mask, trans);
    reduce_kernel<<<1, 256>>>(out);
}

// round 2
// speedup vs baseline: 1.9383x; 1.9383x over previous
#include <cuda_runtime.h>
#include <cstdint>

#define KTAGS 16
#define TLEN  512
#define BROWS 1024
#define START_ID 14
#define STOP_ID  15

__device__ float g_row_out[BROWS];
__device__ int   g_ctr = 0;      // last-block counter, self-resetting

// ---------------------------------------------------------------------------
// Single fused kernel: y-dtype detect (per block, redundant), gold score,
// forward recursion (linear domain, 8-deep emit prefetch, shfl matvec,
// redux-based renorm every 8 steps), last-block mean reduction.
// 128 threads = 8 groups of 16 lanes; one group per batch row. 128 blocks.
// ---------------------------------------------------------------------------
__global__ void __launch_bounds__(128)
crf_fused_kernel(const float* __restrict__ h,
                 const int*   __restrict__ y32,      // raw y words (int32 view)
                 const float* __restrict__ mask,
                 const float* __restrict__ trans,
                 float* __restrict__ out) {
    __shared__ float tr_s[256];
    __shared__ int   s_ysh;
    __shared__ int   s_last;
    __shared__ float s_red[4];

    const int tid = threadIdx.x;

    // ---- load transition matrix to smem ----
    if (tid < 64) {
        ((float4*)tr_s)[tid] = ((const float4*)trans)[tid];
    }

    // ---- y dtype detection (warp 0): sample u64 word row*256 for rows 0..31.
    // int64 layout -> hi word always 0 (values 0..15).
    // int32 layout -> hi = y[row,1], nonzero for any row with len>=2. ----
    if (tid < 32) {
        unsigned long long v = ((const unsigned long long*)y32)[(size_t)tid * 256];
        unsigned bal = __ballot_sync(0xFFFFFFFFu, (unsigned)(v >> 32) != 0u);
        if (tid == 0) s_ysh = (bal == 0u) ? 1 : 0;
    }
    __syncthreads();

    const int lane = tid & 15;
    const int gid  = tid >> 4;                  // 0..7 group in block
    const int row  = blockIdx.x * 8 + gid;
    const unsigned gmask = 0xFFFFu << ((gid & 1) * 16);

    const float* hrow = h    + (size_t)row * TLEN * KTAGS;
    const float* mrow = mask + (size_t)row * TLEN;
    const int ysh = s_ysh;
    const int* yrow = y32 + (((size_t)row * TLEN) << ysh);

    // Etr[i] = exp(trans[lane, i]); exp(-1e4) flushes to 0.
    float Etr[16];
#pragma unroll
    for (int i = 0; i < 16; i++) Etr[i] = __expf(tr_s[lane * 16 + i]);
    const float EtrStop = __expf(tr_s[STOP_ID * 16 + lane]);

    // ---- length + gold score (branchless, lane-parallel, high MLP) ----
    float lsum = 0.f, gsum = 0.f;
#pragma unroll 4
    for (int k = lane; k < TLEN; k += 16) {
        float mk = mrow[k];
        int yt = yrow[k << ysh];
        int yp = (k == 0) ? START_ID : yrow[(k - 1) << ysh];
        lsum += mk;
        gsum = fmaf(mk, hrow[k * 16 + yt] + tr_s[yt * 16 + yp], gsum);
    }
#pragma unroll
    for (int s = 8; s; s >>= 1) {
        lsum += __shfl_xor_sync(gmask, lsum, s, 16);
        gsum += __shfl_xor_sync(gmask, gsum, s, 16);
    }
    const int len = (int)(lsum + 0.5f);
    const int lastTag = yrow[(len - 1) << ysh];
    const float gold = gsum + tr_s[STOP_ID * 16 + lastTag];

    // ---- forward recursion, invariant alpha_j = C + ln(p_j) ----
    float p = (lane == START_ID) ? 1.0f : 0.0f;
    float C = 0.0f;

    // 8-deep emit prefetch pipeline
    float hb[8];
#pragma unroll
    for (int d = 0; d < 8; d++) hb[d] = hrow[d * 16 + lane];

    for (int t0 = 0; t0 < len; t0 += 8) {
        // exp the 8 buffered emits (off the critical chain)
        float eh[8];
#pragma unroll
        for (int u = 0; u < 8; u++) eh[u] = __expf(hb[u]);
        // refill pipeline for steps t0+8 .. t0+15 (clamped, always in-bounds)
#pragma unroll
        for (int u = 0; u < 8; u++) {
            int idx = t0 + u + 8;
            idx = (idx > TLEN - 1) ? (TLEN - 1) : idx;
            hb[u] = hrow[idx * 16 + lane];
        }
#pragma unroll
        for (int u = 0; u < 8; u++) {
            if (t0 + u < len) {
                float q0  = __shfl_sync(gmask, p, 0,  16);
                float q1  = __shfl_sync(gmask, p, 1,  16);
                float q2  = __shfl_sync(gmask, p, 2,  16);
                float q3  = __shfl_sync(gmask, p, 3,  16);
                float q4  = __shfl_sync(gmask, p, 4,  16);
                float q5  = __shfl_sync(gmask, p, 5,  16);
                float q6  = __shfl_sync(gmask, p, 6,  16);
                float q7  = __shfl_sync(gmask, p, 7,  16);
                float q8  = __shfl_sync(gmask, p, 8,  16);
                float q9  = __shfl_sync(gmask, p, 9,  16);
                float q10 = __shfl_sync(gmask, p, 10, 16);
                float q11 = __shfl_sync(gmask, p, 11, 16);
                float q12 = __shfl_sync(gmask, p, 12, 16);
                float q13 = __shfl_sync(gmask, p, 13, 16);
                float q14 = __shfl_sync(gmask, p, 14, 16);
                float q15 = __shfl_sync(gmask, p, 15, 16);

                float m0 = fmaf(q1,  Etr[1],  q0  * Etr[0]);
                float m1 = fmaf(q3,  Etr[3],  q2  * Etr[2]);
                float m2 = fmaf(q5,  Etr[5],  q4  * Etr[4]);
                float m3 = fmaf(q7,  Etr[7],  q6  * Etr[6]);
                float m4 = fmaf(q9,  Etr[9],  q8  * Etr[8]);
                float m5 = fmaf(q11, Etr[11], q10 * Etr[10]);
                float m6 = fmaf(q13, Etr[13], q12 * Etr[12]);
                float m7 = fmaf(q15, Etr[15], q14 * Etr[14]);
                float S = ((m0 + m1) + (m2 + m3)) + ((m4 + m5) + (m6 + m7));
                p = S * eh[u];
            }
        }
        // amortized renormalization (p >= 0, so uint max == float max)
        unsigned ru;
        asm("redux.sync.max.u32 %0, %1, %2;"
            : "=r"(ru) : "r"(__float_as_uint(p)), "r"(gmask));
        float r = fmaxf(__uint_as_float(ru), 1e-37f);
        C += __logf(r);
        p = __fdividef(p, r);
    }

    // fwd = C + ln( sum_j p_j * exp(trans[STOP, j]) )
    float v = p * EtrStop;
#pragma unroll
    for (int s = 8; s; s >>= 1)
        v += __shfl_xor_sync(gmask, v, s, 16);
    const float fwd = C + __logf(v);

    if (lane == 0) g_row_out[row] = fwd - gold;

    // ---- last-block mean reduction ----
    __threadfence();
    __syncthreads();
    if (tid == 0) {
        int old = atomicAdd(&g_ctr, 1);
        s_last = (old == gridDim.x - 1);
    }
    __syncthreads();
    if (s_last) {
        float s = 0.f;
#pragma unroll
        for (int i = 0; i < BROWS / 128; i++)
            s += g_row_out[tid + i * 128];
#pragma unroll
        for (int sft = 16; sft; sft >>= 1)
            s += __shfl_xor_sync(0xFFFFFFFFu, s, sft);
        if ((tid & 31) == 0) s_red[tid >> 5] = s;
        __syncthreads();
        if (tid == 0) {
            float tot = s_red[0] + s_red[1] + s_red[2] + s_red[3];
            out[0] = tot * (1.0f / (float)BROWS);
            g_ctr = 0;   // reset for next graph replay
        }
    }
}

// ---------------------------------------------------------------------------
extern "C" void kernel_launch(void* const* d_in, const int* in_sizes, int n_in,
                              void* d_out, int out_size) {
    const float* h     = (const float*)d_in[0];
    const int*   y     = (const int*)d_in[1];
    const float* mask  = (const float*)d_in[2];
    const float* trans = (const float*)d_in[3];
    float* out = (float*)d_out;

    crf_fused_kernel<<<BROWS / 8, 128>>>(h, y, mask, trans, out);
}

// round 3
// speedup vs baseline: 2.8220x; 1.4560x over previous
#include <cuda_runtime.h>
#include <cstdint>

#define KTAGS 16
#define TLEN  512
#define BROWS 1024
#define START_ID 14
#define STOP_ID  15

__device__ float g_row_out[BROWS];
__device__ int   g_ctr = 0;      // last-block counter, self-resetting

// ---------------------------------------------------------------------------
// Fused kernel: y-dtype detect, gold score, forward recursion (linear domain,
// 8-deep emit prefetch, shfl matvec, branchless warp-uniform loop,
// redux renorm every 8 steps), last-block mean reduction.
// 128 threads = 8 groups of 16 lanes; one group per batch row. 128 blocks.
// ---------------------------------------------------------------------------
__global__ void __launch_bounds__(128)
crf_fused_kernel(const float* __restrict__ h,
                 const int*   __restrict__ y32,      // raw y words (int32 view)
                 const float* __restrict__ mask,
                 const float* __restrict__ trans,
                 float* __restrict__ out) {
    __shared__ float tr_s[256];
    __shared__ int   s_ysh;
    __shared__ int   s_last;
    __shared__ float s_red[4];

    const int tid = threadIdx.x;

    if (tid < 64) ((float4*)tr_s)[tid] = ((const float4*)trans)[tid];

    // y dtype detection: int64 layout -> hi 32-bit word of each u64 is 0.
    if (tid < 32) {
        unsigned long long v = ((const unsigned long long*)y32)[(size_t)tid * 256];
        unsigned bal = __ballot_sync(0xFFFFFFFFu, (unsigned)(v >> 32) != 0u);
        if (tid == 0) s_ysh = (bal == 0u) ? 1 : 0;
    }
    __syncthreads();

    const int lane = tid & 15;
    const int gid  = tid >> 4;                  // 0..7 group in block
    const int row  = blockIdx.x * 8 + gid;
    const unsigned gmask = 0xFFFFu << ((gid & 1) * 16);

    const float* hrow = h    + (size_t)row * TLEN * KTAGS;
    const float* mrow = mask + (size_t)row * TLEN;
    const int ysh = s_ysh;
    const int* yrow = y32 + (((size_t)row * TLEN) << ysh);

    // Etr[i] = exp(trans[lane, i]); exp(-1e4) flushes to 0.
    float Etr[16];
#pragma unroll
    for (int i = 0; i < 16; i++) Etr[i] = __expf(tr_s[lane * 16 + i]);
    const float EtrStop = __expf(tr_s[STOP_ID * 16 + lane]);

    // ---- length + gold score (branchless, lane-parallel) ----
    float lsum = 0.f, gsum = 0.f;
#pragma unroll 4
    for (int k = lane; k < TLEN; k += 16) {
        float mk = mrow[k];
        int yt = yrow[k << ysh];
        int yp = (k == 0) ? START_ID : yrow[(k - 1) << ysh];
        lsum += mk;
        gsum = fmaf(mk, hrow[k * 16 + yt] + tr_s[yt * 16 + yp], gsum);
    }
#pragma unroll
    for (int s = 8; s; s >>= 1) {
        lsum += __shfl_xor_sync(gmask, lsum, s, 16);
        gsum += __shfl_xor_sync(gmask, gsum, s, 16);
    }
    const int len = (int)(lsum + 0.5f);
    const int lastTag = yrow[(len - 1) << ysh];
    const float gold = gsum + tr_s[STOP_ID * 16 + lastTag];

    // warp-uniform trip count: max over both groups, rounded up to 8
    int steps = (len + 7) & ~7;
    steps = max(steps, __shfl_xor_sync(0xFFFFFFFFu, steps, 16));

    // ---- forward recursion, invariant alpha_j = C + ln(p_j) ----
    float p = (lane == START_ID) ? 1.0f : 0.0f;
    float C = 0.0f;

    float hb[8];
#pragma unroll
    for (int d = 0; d < 8; d++) hb[d] = hrow[d * 16 + lane];

    for (int t0 = 0; t0 < steps; t0 += 8) {
        float eh[8];
#pragma unroll
        for (int u = 0; u < 8; u++) eh[u] = __expf(hb[u]);
#pragma unroll
        for (int u = 0; u < 8; u++) {
            int idx = t0 + u + 8;
            idx = (idx > TLEN - 1) ? (TLEN - 1) : idx;
            hb[u] = hrow[idx * 16 + lane];
        }
#pragma unroll
        for (int u = 0; u < 8; u++) {
            const bool act = (t0 + u) < len;     // group-uniform predicate, SEL only
            float q0  = __shfl_sync(gmask, p, 0,  16);
            float q1  = __shfl_sync(gmask, p, 1,  16);
            float q2  = __shfl_sync(gmask, p, 2,  16);
            float q3  = __shfl_sync(gmask, p, 3,  16);
            float q4  = __shfl_sync(gmask, p, 4,  16);
            float q5  = __shfl_sync(gmask, p, 5,  16);
            float q6  = __shfl_sync(gmask, p, 6,  16);
            float q7  = __shfl_sync(gmask, p, 7,  16);
            float q8  = __shfl_sync(gmask, p, 8,  16);
            float q9  = __shfl_sync(gmask, p, 9,  16);
            float q10 = __shfl_sync(gmask, p, 10, 16);
            float q11 = __shfl_sync(gmask, p, 11, 16);
            float q12 = __shfl_sync(gmask, p, 12, 16);
            float q13 = __shfl_sync(gmask, p, 13, 16);
            float q14 = __shfl_sync(gmask, p, 14, 16);
            float q15 = __shfl_sync(gmask, p, 15, 16);

            float m0 = fmaf(q1,  Etr[1],  q0  * Etr[0]);
            float m1 = fmaf(q3,  Etr[3],  q2  * Etr[2]);
            float m2 = fmaf(q5,  Etr[5],  q4  * Etr[4]);
            float m3 = fmaf(q7,  Etr[7],  q6  * Etr[6]);
            float m4 = fmaf(q9,  Etr[9],  q8  * Etr[8]);
            float m5 = fmaf(q11, Etr[11], q10 * Etr[10]);
            float m6 = fmaf(q13, Etr[13], q12 * Etr[12]);
            float m7 = fmaf(q15, Etr[15], q14 * Etr[14]);
            float S = ((m0 + m1) + (m2 + m3)) + ((m4 + m5) + (m6 + m7));
            float pn = S * eh[u];
            p = act ? pn : p;
        }
        // renorm: invariant-preserving for both active and finished rows
        // (finished rows: r == 1 exactly after first post-finish renorm)
        unsigned ru;
        asm("redux.sync.max.u32 %0, %1, %2;"
            : "=r"(ru) : "r"(__float_as_uint(p)), "r"(gmask));
        float r = fmaxf(__uint_as_float(ru), 1e-37f);
        C += __logf(r);
        p = __fdividef(p, r);
    }

    // fwd = C + ln( sum_j p_j * exp(trans[STOP, j]) )
    float v = p * EtrStop;
#pragma unroll
    for (int s = 8; s; s >>= 1)
        v += __shfl_xor_sync(gmask, v, s, 16);
    const float fwd = C + __logf(v);

    if (lane == 0) g_row_out[row] = fwd - gold;

    // ---- last-block mean reduction ----
    __threadfence();
    __syncthreads();
    if (tid == 0) {
        int old = atomicAdd(&g_ctr, 1);
        s_last = (old == gridDim.x - 1);
    }
    __syncthreads();
    if (s_last) {
        float s = 0.f;
#pragma unroll
        for (int i = 0; i < BROWS / 128; i++)
            s += g_row_out[tid + i * 128];
#pragma unroll
        for (int sft = 16; sft; sft >>= 1)
            s += __shfl_xor_sync(0xFFFFFFFFu, s, sft);
        if ((tid & 31) == 0) s_red[tid >> 5] = s;
        __syncthreads();
        if (tid == 0) {
            float tot = s_red[0] + s_red[1] + s_red[2] + s_red[3];
            out[0] = tot * (1.0f / (float)BROWS);
            g_ctr = 0;   // reset for next graph replay
        }
    }
}

// ---------------------------------------------------------------------------
extern "C" void kernel_launch(void* const* d_in, const int* in_sizes, int n_in,
                              void* d_out, int out_size) {
    const float* h     = (const float*)d_in[0];
    const int*   y     = (const int*)d_in[1];
    const float* mask  = (const float*)d_in[2];
    const float* trans = (const float*)d_in[3];
    float* out = (float*)d_out;

    crf_fused_kernel<<<BROWS / 8, 128>>>(h, y, mask, trans, out);
}

// round 4
// speedup vs baseline: 3.4860x; 1.2353x over previous
#include <cuda_runtime.h>
#include <cstdint>

#define KTAGS 16
#define TLEN  512
#define BROWS 1024
#define START_ID 14
#define STOP_ID  15

__device__ float g_row_out[BROWS];
__device__ int   g_ctr = 0;      // last-block counter, self-resetting

// ---- f32x2 packed helpers (ptxas never auto-fuses these) ----
__device__ __forceinline__ unsigned long long pk2(float lo, float hi) {
    unsigned long long r;
    asm("mov.b64 %0, {%1, %2};" : "=l"(r) : "f"(lo), "f"(hi));
    return r;
}
__device__ __forceinline__ unsigned long long mul2(unsigned long long a, unsigned long long b) {
    unsigned long long r;
    asm("mul.rn.f32x2 %0, %1, %2;" : "=l"(r) : "l"(a), "l"(b));
    return r;
}
__device__ __forceinline__ unsigned long long fma2(unsigned long long a, unsigned long long b,
                                                   unsigned long long c) {
    unsigned long long r;
    asm("fma.rn.f32x2 %0, %1, %2, %3;" : "=l"(r) : "l"(a), "l"(b), "l"(c));
    return r;
}
__device__ __forceinline__ unsigned long long add2(unsigned long long a, unsigned long long b) {
    unsigned long long r;
    asm("add.rn.f32x2 %0, %1, %2;" : "=l"(r) : "l"(a), "l"(b));
    return r;
}
__device__ __forceinline__ float hadd2(unsigned long long a) {
    float lo, hi;
    asm("mov.b64 {%0, %1}, %2;" : "=f"(lo), "=f"(hi) : "l"(a));
    return lo + hi;
}

// ---------------------------------------------------------------------------
// Fused kernel. 128 threads = 8 groups of 16 lanes; one group per batch row.
// Forward recursion in linear domain: alpha_j = C + ln(p_j).
// Exchange of p via double-buffered smem (1 STS + 1 syncwarp + 4 LDS.128).
// Matvec in packed f32x2. Exponent-only renorm every 8 steps.
// ---------------------------------------------------------------------------
__global__ void __launch_bounds__(128)
crf_fused_kernel(const float* __restrict__ h,
                 const int*   __restrict__ y32,      // raw y words (int32 view)
                 const float* __restrict__ mask,
                 const float* __restrict__ trans,
                 float* __restrict__ out) {
    __shared__ float tr_s[256];
    __shared__ float pbuf[2][8][16];    // [parity][group][state]
    __shared__ int   s_ysh;
    __shared__ int   s_last;
    __shared__ float s_red[4];

    const int tid = threadIdx.x;

    if (tid < 64) ((float4*)tr_s)[tid] = ((const float4*)trans)[tid];

    // y dtype detection: int64 layout -> hi 32-bit word of each u64 is 0.
    if (tid < 32) {
        unsigned long long v = ((const unsigned long long*)y32)[(size_t)tid * 256];
        unsigned bal = __ballot_sync(0xFFFFFFFFu, (unsigned)(v >> 32) != 0u);
        if (tid == 0) s_ysh = (bal == 0u) ? 1 : 0;
    }
    __syncthreads();

    const int lane = tid & 15;
    const int gid  = tid >> 4;                  // 0..7 group in block
    const int row  = blockIdx.x * 8 + gid;
    const unsigned gmask = 0xFFFFu << ((gid & 1) * 16);

    const float* hrow = h    + (size_t)row * TLEN * KTAGS;
    const float* mrow = mask + (size_t)row * TLEN;
    const int ysh = s_ysh;
    const int* yrow = y32 + (((size_t)row * TLEN) << ysh);

    // Etr[i] = exp(trans[lane, i]); exp(-1e4) flushes to 0. Packed in pairs.
    unsigned long long EtrP[8];
#pragma unroll
    for (int k = 0; k < 8; k++)
        EtrP[k] = pk2(__expf(tr_s[lane * 16 + 2 * k]),
                      __expf(tr_s[lane * 16 + 2 * k + 1]));
    const float EtrStop = __expf(tr_s[STOP_ID * 16 + lane]);

    // ---- length + gold score (branchless, lane-parallel) ----
    float lsum = 0.f, gsum = 0.f;
#pragma unroll 4
    for (int k = lane; k < TLEN; k += 16) {
        float mk = mrow[k];
        int yt = yrow[k << ysh];
        int yp = (k == 0) ? START_ID : yrow[(k - 1) << ysh];
        lsum += mk;
        gsum = fmaf(mk, hrow[k * 16 + yt] + tr_s[yt * 16 + yp], gsum);
    }
#pragma unroll
    for (int s = 8; s; s >>= 1) {
        lsum += __shfl_xor_sync(gmask, lsum, s, 16);
        gsum += __shfl_xor_sync(gmask, gsum, s, 16);
    }
    const int len = (int)(lsum + 0.5f);
    const int lastTag = yrow[(len - 1) << ysh];
    const float gold = gsum + tr_s[STOP_ID * 16 + lastTag];

    // warp-uniform trip count: max over both groups, rounded up to 8
    int steps = (len + 7) & ~7;
    steps = max(steps, __shfl_xor_sync(0xFFFFFFFFu, steps, 16));

    // ---- forward recursion ----
    float p = (lane == START_ID) ? 1.0f : 0.0f;
    float C = 0.0f;

    float hb[8];
#pragma unroll
    for (int d = 0; d < 8; d++) hb[d] = hrow[d * 16 + lane];

    for (int t0 = 0; t0 < steps; t0 += 8) {
        float eh[8];
#pragma unroll
        for (int u = 0; u < 8; u++) eh[u] = __expf(hb[u]);
#pragma unroll
        for (int u = 0; u < 8; u++) {
            int idx = t0 + u + 8;
            idx = (idx > TLEN - 1) ? (TLEN - 1) : idx;
            hb[u] = hrow[idx * 16 + lane];
        }
#pragma unroll
        for (int u = 0; u < 8; u++) {
            const bool act = (t0 + u) < len;     // group-uniform -> SEL only
            float* buf = pbuf[u & 1][gid];
            buf[lane] = p;
            __syncwarp();
            const float4* bp = (const float4*)buf;
            float4 A = bp[0], B = bp[1], Cv = bp[2], D = bp[3];

            unsigned long long a0 = fma2(pk2(A.z, A.w),  EtrP[1], mul2(pk2(A.x, A.y),  EtrP[0]));
            unsigned long long a1 = fma2(pk2(B.z, B.w),  EtrP[3], mul2(pk2(B.x, B.y),  EtrP[2]));
            unsigned long long a2 = fma2(pk2(Cv.z, Cv.w), EtrP[5], mul2(pk2(Cv.x, Cv.y), EtrP[4]));
            unsigned long long a3 = fma2(pk2(D.z, D.w),  EtrP[7], mul2(pk2(D.x, D.y),  EtrP[6]));
            unsigned long long b0 = add2(a0, a1);
            unsigned long long b1 = add2(a2, a3);
            float S = hadd2(add2(b0, b1));
            float pn = S * eh[u];
            p = act ? pn : p;
        }
        // exponent-only renorm (exact; no-op for finished rows)
        unsigned ru;
        asm("redux.sync.max.u32 %0, %1, %2;"
            : "=r"(ru) : "r"(__float_as_uint(p)), "r"(gmask));
        int me = (int)(ru >> 23);
        me = (me < 1) ? 1 : me;
        float scale = __uint_as_float((unsigned)(254 - me) << 23);  // 2^(127-me)
        C += (float)(me - 127) * 0.6931471805599453f;
        p *= scale;
    }

    // fwd = C + ln( sum_j p_j * exp(trans[STOP, j]) )
    float v = p * EtrStop;
#pragma unroll
    for (int s = 8; s; s >>= 1)
        v += __shfl_xor_sync(gmask, v, s, 16);
    const float fwd = C + __logf(v);

    if (lane == 0) g_row_out[row] = fwd - gold;

    // ---- last-block mean reduction ----
    __threadfence();
    __syncthreads();
    if (tid == 0) {
        int old = atomicAdd(&g_ctr, 1);
        s_last = (old == gridDim.x - 1);
    }
    __syncthreads();
    if (s_last) {
        float s = 0.f;
#pragma unroll
        for (int i = 0; i < BROWS / 128; i++)
            s += g_row_out[tid + i * 128];
#pragma unroll
        for (int sft = 16; sft; sft >>= 1)
            s += __shfl_xor_sync(0xFFFFFFFFu, s, sft);
        if ((tid & 31) == 0) s_red[tid >> 5] = s;
        __syncthreads();
        if (tid == 0) {
            float tot = s_red[0] + s_red[1] + s_red[2] + s_red[3];
            out[0] = tot * (1.0f / (float)BROWS);
            g_ctr = 0;   // reset for next graph replay
        }
    }
}

// ---------------------------------------------------------------------------
extern "C" void kernel_launch(void* const* d_in, const int* in_sizes, int n_in,
                              void* d_out, int out_size) {
    const float* h     = (const float*)d_in[0];
    const int*   y     = (const int*)d_in[1];
    const float* mask  = (const float*)d_in[2];
    const float* trans = (const float*)d_in[3];
    float* out = (float*)d_out;

    crf_fused_kernel<<<BROWS / 8, 128>>>(h, y, mask, trans, out);
}